// round 10
// baseline (speedup 1.0000x reference)
#include <cuda_runtime.h>
#include <cstdint>

// CTC forward, LOG2 domain, pure f32 — DECOUPLED WARP PIPELINE (no CTA
// barrier in the main loop). 13 warps, 2 states/thread (E=blank, O=label),
// alpha in REGISTERS. Warp w needs only warp w-1's top odd state at step
// t-1: published as a single 64-bit {value,tag} smem transaction into a
// 64-deep ring; readers spin on the tag. Backpressure via per-warp
// consumed counters. Batch mean folded in via last-CTA atomic.

#define T_DIM 2000
#define V_DIM 256
#define S_DIM 400
#define L_DIM 801
#define NT    416          // 13 warps
#define NW    13
#define DPTH  64           // ring depth (power of 2)
#define QD    4            // logp prefetch depth
#define NEGF  (-1e30f)

__device__ float g_partial[64];
__device__ int   g_ctr = 0;

__device__ __forceinline__ float ex2f(float x) {
    float y; asm("ex2.approx.f32 %0, %1;" : "=f"(y) : "f"(x)); return y;
}
__device__ __forceinline__ float lg2f(float x) {
    float y; asm("lg2.approx.f32 %0, %1;" : "=f"(y) : "f"(x)); return y;
}
__device__ __forceinline__ uint32_t su32(const void* p) {
    return (uint32_t)__cvta_generic_to_shared(p);
}

__global__ __launch_bounds__(NT, 1)
void ctc_kernel(const float* __restrict__ logp,
                const int*   __restrict__ targets,
                const int*   __restrict__ ilen,
                const int*   __restrict__ tlen,
                float*       __restrict__ out,
                int B)
{
    __shared__ uint2 ring[NW][DPTH];   // {float bits, tag}
    __shared__ int   cons[NW];
    __shared__ float finE[NT], finO[NT];

    const int b    = blockIdx.x;
    const int tid  = threadIdx.x;
    const int lane = tid & 31;
    const int w    = tid >> 5;
    const float* lpb = logp + (size_t)b * T_DIM * V_DIM;
    const int il  = ilen[b];
    const int tl  = tlen[b];
    const int end = 2 * tl;
    const int lim = il - 1;
    const float l2e = 1.4426950408889634f;

    // thread owns pair k=tid: E = state 2k (blank), O = state 2k+1 (label)
    int  lbl  = 1;
    bool skip = false;
    if (tid < S_DIM) {
        lbl = targets[b * S_DIM + tid];
        if (tid >= 1) skip = (lbl != targets[b * S_DIM + tid - 1]);
    }
    const bool ve = (tid <= 400) && (2 * tid     <= end);
    const bool vo = (tid <= 399) && (2 * tid + 1 <= end);
    const float* gbp = lpb + 1;      // blank column
    const float* glp = lpb + lbl;    // own-label column

    // init ring: slot 0 primed {NEG, tag 0} (O31 at t=0 is NEG everywhere);
    // other slots get an impossible tag.
    for (int i = tid; i < NW * DPTH; i += NT)
        ((uint2*)ring)[i] = make_uint2(__float_as_uint(NEGF),
                                       (i % DPTH == 0) ? 0u : 0x7fffffffu);
    if (tid < NW) cons[tid] = 0;

    // t = 0: alpha0[0] = lp(0,blank), alpha0[1] = lp(0,l1); rest NEG
    float E = NEGF, O = NEGF;
    if (tid == 0) { E = lpb[1] * l2e; O = lpb[lbl] * l2e; }

    // prefetch queues, rows 1..4
    float qb0 = gbp[(size_t)min(1, lim) * V_DIM];
    float qb1 = gbp[(size_t)min(2, lim) * V_DIM];
    float qb2 = gbp[(size_t)min(3, lim) * V_DIM];
    float qb3 = gbp[(size_t)min(4, lim) * V_DIM];
    float ql0 = glp[(size_t)min(1, lim) * V_DIM];
    float ql1 = glp[(size_t)min(2, lim) * V_DIM];
    float ql2 = glp[(size_t)min(3, lim) * V_DIM];
    float ql3 = glp[(size_t)min(4, lim) * V_DIM];
    __syncthreads();                 // ring/cons init visible

    const uint32_t rbase   = su32(&ring[(w > 0) ? w - 1 : 0][0]);
    const uint32_t wbase   = su32(&ring[w][0]);
    const uint32_t consNxt = su32(&cons[(w < NW - 1) ? w + 1 : w]);
    const uint32_t consOwn = su32(&cons[w]);
    int lastCons = 0;                // used by lane 31 only

    #pragma unroll 4
    for (int t = 1; t < il; ++t) {
        // halo: O[32w-1] at step t-1 from warp below (single 64b load, spin)
        float hbO = NEGF;
        if (w > 0) {
            uint32_t addr = rbase + ((unsigned)(t - 1) & (DPTH - 1)) * 8u;
            unsigned fa, tg;
            do {
                asm volatile("ld.volatile.shared.v2.u32 {%0,%1}, [%2];"
                             : "=r"(fa), "=r"(tg) : "r"(addr));
            } while ((int)tg != t - 1);
            hbO = __uint_as_float(fa);
        }
        float Oup  = __shfl_up_sync(0xffffffffu, O, 1);
        float ylow = (lane == 0) ? hbO : Oup;         // O[k-1] at t-1

        // E' = logaddexp2(E, O[k-1]) + lp_blank
        float me = fmaxf(E, ylow);
        float sE = 1.0f + ex2f(-fabsf(E - ylow));
        float nE = fmaf(qb0, l2e, me + lg2f(sE));

        // O' = logaddexp2_3(O, E, skip? O[k-1]) + lp_label
        float z  = skip ? ylow : NEGF;
        float mo = fmaxf(fmaxf(O, E), z);
        float sO = ex2f(O - mo) + ex2f(E - mo) + ex2f(z - mo);
        float nO = fmaf(ql0, l2e, mo + lg2f(sO));

        E = ve ? nE : NEGF;
        O = vo ? nO : NEGF;

        // publish top odd state {O31, t} (warps 0..11, lane 31)
        if (w < NW - 1 && lane == 31) {
            if (t - lastCons >= DPTH - 4) {           // backpressure (rare)
                do {
                    asm volatile("ld.volatile.shared.s32 %0, [%1];"
                                 : "=r"(lastCons) : "r"(consNxt));
                } while (t - lastCons >= DPTH - 4);
            }
            uint32_t addr = wbase + ((unsigned)t & (DPTH - 1)) * 8u;
            asm volatile("st.volatile.shared.v2.u32 [%0], {%1,%2};"
                         :: "r"(addr), "r"(__float_as_uint(O)), "r"((unsigned)t));
        }
        // progress publish (readers, lane 0)
        if (w > 0 && lane == 0)
            asm volatile("st.volatile.shared.s32 [%0], %1;"
                         :: "r"(consOwn), "r"(t));

        // rotate prefetch queues, fetch row t+QD (clamped)
        qb0 = qb1; qb1 = qb2; qb2 = qb3;
        ql0 = ql1; ql1 = ql2; ql2 = ql3;
        {
            int rr = t + QD; rr = rr < lim ? rr : lim;
            qb3 = gbp[(size_t)rr * V_DIM];
            ql3 = glp[(size_t)rr * V_DIM];
        }
    }

    // collect final states; all warps ran exactly il-1 steps -> barrier legal
    finE[tid] = E; finO[tid] = O;
    __syncthreads();

    if (tid == 0) {
        float x = finE[tl];          // state 2*tl
        float y = finO[tl - 1];      // state 2*tl - 1
        float m = fmaxf(x, y);
        float ll2 = m + lg2f(ex2f(x - m) + ex2f(y - m));
        float loss = -0.6931471805599453f * ll2;
        if (!(loss < 1e29f)) loss = 0.0f;
        g_partial[b] = loss / (float)tl;
        __threadfence();
        int done = atomicAdd(&g_ctr, 1);
        if (done == B - 1) {
            float v = 0.0f;
            for (int i = 0; i < B; ++i) v += g_partial[i];
            out[0] = v / (float)B;
            g_ctr = 0;               // deterministic across graph replays
        }
    }
}

extern "C" void kernel_launch(void* const* d_in, const int* in_sizes, int n_in,
                              void* d_out, int out_size)
{
    const float* logp    = (const float*)d_in[0];
    const int*   targets = (const int*)d_in[1];
    const int*   il      = (const int*)d_in[2];
    const int*   tl      = (const int*)d_in[3];
    const int B = in_sizes[2];

    ctc_kernel<<<B, NT>>>(logp, targets, il, tl, (float*)d_out, B);
}

// round 13
// speedup vs baseline: 3.0624x; 3.0624x over previous
#include <cuda_runtime.h>
#include <cstdint>

// CTC forward-backward split, LOG2 domain, pure f32.
// 128 CTAs: CTA b (b<64) computes ALPHA for batch b over t=0..m-1;
// CTA 64+b computes BETA for batch b over t=il-1..m (m=il/2), then
// gamma[s] = beta_m[s] (+) beta_m[s+1] (+) skip? beta_m[s+2], publishes to
// global + flag. Alpha CTA combines: ll = logsum_s alpha_{m-1}[s]+gamma[s].
// Inner loop identical to the measured-best R7 structure (26 warps,
// 1 state/thread, smem alpha, one barrier/step, per-thread logp prefetch).

#define T_DIM 2000
#define V_DIM 256
#define S_DIM 400
#define L_DIM 801
#define NTHREADS 832        // 26 warps
#define QD 6
#define NEGF (-1e30f)

__device__ float g_partial[64];
__device__ float g_gamma[64][804];
__device__ int   g_flag[64];     // zero-init; alpha resets after consume
__device__ int   g_ctr = 0;

__device__ __forceinline__ float ex2f(float x) {
    float y; asm("ex2.approx.f32 %0, %1;" : "=f"(y) : "f"(x)); return y;
}
__device__ __forceinline__ float lg2f(float x) {
    float y; asm("lg2.approx.f32 %0, %1;" : "=f"(y) : "f"(x)); return y;
}

__global__ __launch_bounds__(NTHREADS, 1)
void ctc_kernel(const float* __restrict__ logp,
                const int*   __restrict__ targets,
                const int*   __restrict__ ilen,
                const int*   __restrict__ tlen,
                float*       __restrict__ out,
                int B)
{
    __shared__ float buf[2][NTHREADS + 4];   // alpha: [2+s]; beta: [s], pad top
    __shared__ float red[32];
    __shared__ float Msh, Ssh;

    const int b     = blockIdx.x & 63;
    const bool isA  = blockIdx.x < 64;
    const int tid   = threadIdx.x;
    const int lane  = tid & 31;
    const int w     = tid >> 5;
    const float* lpb = logp + (size_t)b * T_DIM * V_DIM;
    const int il  = ilen[b];
    const int tl  = tlen[b];
    const int end = 2 * tl;
    const int m   = il >> 1;                 // meet point (1 <= m <= il-1)
    const float l2e = 1.4426950408889634f;
    const int s = tid;

    // per-thread column / skip flags
    int  lbl = 1;
    bool skA = false, skB = false;
    if ((s & 1) && s < L_DIM) {
        const int* tgt = targets + b * S_DIM;
        lbl = tgt[s >> 1];
        if (s >= 3) skA = (lbl != tgt[(s - 2) >> 1]);          // alpha: from s-2
        if (s + 2 < L_DIM) skB = (tgt[(s + 2) >> 1] != lbl);   // beta: to s+2
    }
    const bool valid = (s < L_DIM) && (s <= end);
    const float* gcol = lpb + lbl;

    // fill both parities with NEG
    for (int i = tid; i < 2 * (NTHREADS + 4); i += NTHREADS)
        ((float*)buf)[i] = NEGF;
    __syncthreads();

    if (isA) {
        // ================= ALPHA: t = 0 .. m-1 =================
        const int lim = m - 1;
        if (tid == 0) buf[0][2] = lpb[1] * l2e;
        if (tid == 1 && valid) buf[0][3] = lpb[lbl] * l2e;

        float q0 = gcol[(size_t)min(1, lim) * V_DIM];
        float q1 = gcol[(size_t)min(2, lim) * V_DIM];
        float q2 = gcol[(size_t)min(3, lim) * V_DIM];
        float q3 = gcol[(size_t)min(4, lim) * V_DIM];
        float q4 = gcol[(size_t)min(5, lim) * V_DIM];
        float q5 = gcol[(size_t)min(6, lim) * V_DIM];
        __syncthreads();

        for (int t = 1; t <= lim; ++t) {
            const float* prev = &buf[(t + 1) & 1][2];
            float*       cur  = &buf[t & 1][2];
            float a  = prev[s];
            float a1 = prev[s - 1];
            float a2 = skA ? prev[s - 2] : NEGF;
            float mm = fmaxf(fmaxf(a, a1), a2);
            float sm = ex2f(a - mm) + ex2f(a1 - mm) + ex2f(a2 - mm);
            float nv = fmaf(q0, l2e, mm + lg2f(sm));
            cur[s] = valid ? nv : NEGF;
            q0 = q1; q1 = q2; q2 = q3; q3 = q4; q4 = q5;
            { int rr = t + QD; rr = rr < lim ? rr : lim;
              q5 = gcol[(size_t)rr * V_DIM]; }
            __syncthreads();
        }

        // ---- wait for gamma, combine ----
        if (tid == 0) {
            volatile int* fl = &g_flag[b];
            while (*fl == 0) { }
            __threadfence();
        }
        __syncthreads();

        const float* afin = &buf[(m - 1) & 1][2];
        float x = (s < L_DIM) ? (afin[s] + g_gamma[b][s]) : NEGF;

        // block logsumexp2
        float wm = x;
        #pragma unroll
        for (int o = 16; o; o >>= 1)
            wm = fmaxf(wm, __shfl_xor_sync(0xffffffffu, wm, o));
        if (lane == 0) red[w] = wm;
        __syncthreads();
        if (tid == 0) {
            float M = NEGF;
            for (int i = 0; i < 26; ++i) M = fmaxf(M, red[i]);
            Msh = M;
        }
        __syncthreads();
        float e = ex2f(x - Msh);
        #pragma unroll
        for (int o = 16; o; o >>= 1)
            e += __shfl_xor_sync(0xffffffffu, e, o);
        if (lane == 0) red[w] = e;
        __syncthreads();

        if (tid == 0) {
            float tot = 0.0f;
            for (int i = 0; i < 26; ++i) tot += red[i];
            float ll2 = Msh + lg2f(tot);
            float loss = -0.6931471805599453f * ll2;
            if (!(loss < 1e29f)) loss = 0.0f;
            g_partial[b] = loss / (float)tl;
            g_flag[b] = 0;                     // reset for next graph replay
            __threadfence();
            int done = atomicAdd(&g_ctr, 1);
            if (done == B - 1) {
                float v = 0.0f;
                for (int i = 0; i < B; ++i) v += g_partial[i];
                out[0] = v / (float)B;
                g_ctr = 0;
            }
        }
    } else {
        // ================= BETA: t = il-1 .. m =================
        // init at t = il-1
        if (s == end || s == end - 1)
            buf[(il - 1) & 1][s] = gcol[(size_t)(il - 1) * V_DIM] * l2e;

        // descending prefetch: rows il-2, il-3, ... (clamped at m)
        auto rowclamp = [&](int r) { return r > m ? r : m; };
        float q0 = gcol[(size_t)rowclamp(il - 2) * V_DIM];
        float q1 = gcol[(size_t)rowclamp(il - 3) * V_DIM];
        float q2 = gcol[(size_t)rowclamp(il - 4) * V_DIM];
        float q3 = gcol[(size_t)rowclamp(il - 5) * V_DIM];
        float q4 = gcol[(size_t)rowclamp(il - 6) * V_DIM];
        float q5 = gcol[(size_t)rowclamp(il - 7) * V_DIM];
        __syncthreads();

        for (int t = il - 2; t >= m; --t) {
            const float* prev = buf[(t + 1) & 1];
            float*       cur  = buf[t & 1];
            float a  = prev[s];
            float a1 = prev[s + 1];
            float a2 = skB ? prev[s + 2] : NEGF;
            float mm = fmaxf(fmaxf(a, a1), a2);
            float sm = ex2f(a - mm) + ex2f(a1 - mm) + ex2f(a2 - mm);
            float nv = fmaf(q0, l2e, mm + lg2f(sm));
            cur[s] = valid ? nv : NEGF;
            q0 = q1; q1 = q2; q2 = q3; q3 = q4; q4 = q5;
            { int rr = t - QD; rr = rr > m ? rr : m;
              q5 = gcol[(size_t)rr * V_DIM]; }
            __syncthreads();
        }

        // gamma[s] = laexp2(beta[s], beta[s+1], skB? beta[s+2])
        const float* bm = buf[m & 1];
        if (s < L_DIM) {
            float a  = bm[s];
            float a1 = bm[s + 1];
            float a2 = skB ? bm[s + 2] : NEGF;
            float mm = fmaxf(fmaxf(a, a1), a2);
            float g;
            if (mm <= NEGF) g = NEGF;
            else g = mm + lg2f(ex2f(a - mm) + ex2f(a1 - mm) + ex2f(a2 - mm));
            g_gamma[b][s] = g;
        }
        __threadfence();
        __syncthreads();
        if (tid == 0) g_flag[b] = 1;
    }
}

extern "C" void kernel_launch(void* const* d_in, const int* in_sizes, int n_in,
                              void* d_out, int out_size)
{
    const float* logp    = (const float*)d_in[0];
    const int*   targets = (const int*)d_in[1];
    const int*   il      = (const int*)d_in[2];
    const int*   tl      = (const int*)d_in[3];
    const int B = in_sizes[2];

    ctc_kernel<<<2 * B, NTHREADS>>>(logp, targets, il, tl, (float*)d_out, B);
}